// round 6
// baseline (speedup 1.0000x reference)
#include <cuda_runtime.h>
#include <cstdint>
#include <cstddef>

#define BB 2
#define NN 100
#define HH 800
#define WW 1344
#define PP (HH*WW)          // 1075200 pixels per batch
#define WORDS (PP/32)       // 33600 32-pixel words
#define G 10                // group size
#define NG (NN/G)           // 10 groups
#define HSIZE (1<<G)        // 1024 histogram buckets
#define NSEM 134
#define TPB 256
#define WBLK ((WORDS + TPB - 1)/TPB)   // 132

#define MASK_ELEMS (BB*NN*PP)   // 215040000
#define SEM_ELEMS  (BB*PP)      // 2150400

// ---------------- device state (scratch; re-derived every launch) ----------
__device__ uint32_t g_planes[BB][NN][WORDS];   // bitplanes by RANK (sorted order)
__device__ uint32_t g_claimed[BB][WORDS];      // claimed-pixel bitplane
__device__ int      g_order[BB][NN];           // rank -> original instance idx
__device__ float    g_sscore[BB][NN];          // score by rank
__device__ int      g_scls[BB][NN];            // class id by rank
__device__ int      g_area[BB][NN];            // mask area by rank
__device__ int      g_hist[BB][NG][HSIZE];     // unclaimed-pixel pattern histogram
__device__ int      g_interA[BB][NG][G];       // |mask ∩ claimed-before-group|
__device__ unsigned g_ticket[BB][NG];
__device__ int      g_keptmask[BB][NG];        // per-group kept bitmask
__device__ int      g_nkept[BB];
__device__ int      g_kept_rank[BB][NN];       // compact kept list (ascending rank)
__device__ int      g_kept_val[BB][NN];        // pan value cls + iid*1000
__device__ int      g_next_iid[BB];
__device__ int      g_cls_counts[BB][NSEM];    // stuff class counts (unclaimed px)
// transport flags (re-detected every launch; deterministic)
__device__ int      g_a_is_cls;                // 1 if small buffer A holds class ids
__device__ int      g_cls_f32;                 // class ids on wire as f32 values
__device__ int      g_sem_f32;                 // sem labels on wire as f32 values
__device__ int      g_mask_byte;               // masks byte-packed (else 4-byte words)

// ---------------- init: zero all scratch (must rerun every replay) ---------
__global__ void k_init() {
    int idx = blockIdx.x * blockDim.x + threadIdx.x;
    int stride = gridDim.x * blockDim.x;
    uint32_t* cl = &g_claimed[0][0];
    for (int i = idx; i < BB*WORDS; i += stride) cl[i] = 0u;
    int* h = &g_hist[0][0][0];
    for (int i = idx; i < BB*NG*HSIZE; i += stride) h[i] = 0;
    int* ia = &g_interA[0][0][0];
    for (int i = idx; i < BB*NG*G; i += stride) ia[i] = 0;
    unsigned* tk = &g_ticket[0][0];
    int* km = &g_keptmask[0][0];
    for (int i = idx; i < BB*NG; i += stride) { tk[i] = 0u; km[i] = 0; }
    int* ar = &g_area[0][0];
    for (int i = idx; i < BB*NN; i += stride) ar[i] = 0;
    int* cc = &g_cls_counts[0][0];
    for (int i = idx; i < BB*NSEM; i += stride) cc[i] = 0;
    if (idx < BB) { g_nkept[idx] = 0; g_next_iid[idx] = 1; }
}

// ---------------- runtime transport classification --------------------------
__device__ __forceinline__ bool int_in(unsigned int raw, int lo, int hi) {
    int v = (int)raw; return v >= lo && v < hi;
}
__device__ __forceinline__ bool f32_in(unsigned int raw, int lo, int hi) {
    float f = __uint_as_float(raw);
    if (!(f >= (float)lo && f < (float)hi)) return false;   // NaN-safe
    return floorf(f) == f;
}

__global__ void k_detect(const unsigned int* __restrict__ pa,
                         const unsigned int* __restrict__ pb,
                         const unsigned int* __restrict__ sem,
                         const unsigned int* __restrict__ masks) {
    __shared__ int f_ai, f_af, f_bi, f_bf, f_si, f_sf, f_w;
    int t = threadIdx.x;
    if (t == 0) { f_ai=1; f_af=1; f_bi=1; f_bf=1; f_si=1; f_sf=1; f_w=1; }
    __syncthreads();
    if (t < BB*NN) {
        unsigned int va = pa[t], vb = pb[t];
        if (!int_in(va, 0, 80)) f_ai = 0;
        if (!f32_in(va, 0, 80)) f_af = 0;
        if (!int_in(vb, 0, 80)) f_bi = 0;
        if (!f32_in(vb, 0, 80)) f_bf = 0;
    }
    #pragma unroll
    for (int k = 0; k < 4; k++) {
        int i = (t + 256*k) * (SEM_ELEMS/1024);
        unsigned int v = sem[i];
        if (!int_in(v, 0, NSEM)) f_si = 0;
        if (!f32_in(v, 0, NSEM)) f_sf = 0;
    }
    #pragma unroll
    for (int k = 0; k < 4; k++) {
        unsigned int v = masks[t + 256*k];
        if (!(v == 0u || v == 1u || v == 0x3F800000u)) f_w = 0;
    }
    __syncthreads();
    if (t == 0) {
        int a_cls = (f_ai | f_af);
        g_a_is_cls = a_cls;
        g_cls_f32  = a_cls ? (f_af && !f_ai) : (f_bf && !f_bi);
        g_sem_f32  = (f_sf && !f_si);
        g_mask_byte = f_w ? 0 : 1;
    }
}

// ---------------- stable descending sort of 100 scores per batch -----------
__global__ void k_sort(const unsigned int* __restrict__ pa,
                       const unsigned int* __restrict__ pb) {
    const unsigned int* scores = g_a_is_cls ? pb : pa;
    const unsigned int* cls    = g_a_is_cls ? pa : pb;
    int clsf = g_cls_f32;
    __shared__ float ss[BB][NN];
    int t = threadIdx.x;
    for (int i = t; i < BB*NN; i += blockDim.x)
        ss[i/NN][i%NN] = __uint_as_float(scores[i]);   // scores always f32 bits
    __syncthreads();
    for (int idx = t; idx < BB*NN; idx += blockDim.x) {
        int b = idx / NN, i = idx % NN;
        float si = ss[b][i];
        int r = 0;
        #pragma unroll 4
        for (int j = 0; j < NN; j++) {
            float sj = ss[b][j];
            r += (sj > si) || (sj == si && j < i);   // stable desc rank
        }
        unsigned int rawc = cls[b*NN + i];
        int c = clsf ? (int)__uint_as_float(rawc) : (int)rawc;
        g_order[b][r]  = i;
        g_sscore[b][r] = si;
        g_scls[b][r]   = c;
    }
}

// ---------------- pack masks into bitplanes + areas --------------------------
__global__ void k_pack(const unsigned int* __restrict__ masks) {
    int b = blockIdx.z, r = blockIdx.y;
    int w = blockIdx.x * TPB + threadIdx.x;
    bool cand = (g_sscore[b][r] >= 0.5f);
    uint32_t bits = 0;
    if (w < WORDS && cand) {
        int orig = g_order[b][r];
        size_t base = (size_t)(b*NN + orig) * PP + (size_t)w * 32;
        if (g_mask_byte) {
            const uint4* q = (const uint4*)((const unsigned char*)masks + base);
            uint4 x = q[0], y = q[1];
            uint32_t v[8] = {x.x, x.y, x.z, x.w, y.x, y.y, y.z, y.w};
            #pragma unroll
            for (int j = 0; j < 8; j++) {
                uint32_t nv = (v[j] | (v[j] >> 7) | (v[j] >> 14) | (v[j] >> 21)) & 0xFu;
                bits |= nv << (4*j);
            }
        } else {
            const uint4* q = (const uint4*)(masks + base);
            #pragma unroll
            for (int j = 0; j < 8; j++) {
                uint4 x = q[j];
                bits |= (uint32_t)(x.x != 0u) << (4*j + 0);
                bits |= (uint32_t)(x.y != 0u) << (4*j + 1);
                bits |= (uint32_t)(x.z != 0u) << (4*j + 2);
                bits |= (uint32_t)(x.w != 0u) << (4*j + 3);
            }
        }
    }
    if (w < WORDS) g_planes[b][r][w] = bits;
    int pc = __popc(bits);
    #pragma unroll
    for (int o = 16; o; o >>= 1) pc += __shfl_down_sync(0xffffffffu, pc, o);
    __shared__ int sa[TPB/32];
    if ((threadIdx.x & 31) == 0) sa[threadIdx.x >> 5] = pc;
    __syncthreads();
    if (threadIdx.x == 0) {
        int s = 0;
        #pragma unroll
        for (int k = 0; k < TPB/32; k++) s += sa[k];
        if (s) atomicAdd(&g_area[b][r], s);
    }
}

// ---------------- per-group phase: histogram + (last block) decisions ------
__global__ void k_phase(int g) {
    int b = blockIdx.y;
    int w = blockIdx.x * TPB + threadIdx.x;
    __shared__ int s_hist[HSIZE];
    __shared__ int s_a[G];
    __shared__ unsigned s_old;
    for (int i = threadIdx.x; i < HSIZE; i += TPB) s_hist[i] = 0;
    if (threadIdx.x < G) s_a[threadIdx.x] = 0;
    __syncthreads();

    int a_loc[G];
    #pragma unroll
    for (int i = 0; i < G; i++) a_loc[i] = 0;

    if (w < WORDS) {
        uint32_t c = g_claimed[b][w];
        if (g > 0) {
            int km = g_keptmask[b][g-1];
            int pbase = (g-1)*G;
            while (km) { int i = __ffs(km) - 1; km &= km - 1; c |= g_planes[b][pbase+i][w]; }
            g_claimed[b][w] = c;
        }
        int base = g*G;
        uint32_t pw[G];
        #pragma unroll
        for (int i = 0; i < G; i++) pw[i] = g_planes[b][base+i][w];
        #pragma unroll
        for (int i = 0; i < G; i++) a_loc[i] = __popc(pw[i] & c);
        uint32_t u = ~c;   // histogram only unclaimed pixels
        while (u) {
            int p = __ffs(u) - 1; u &= u - 1;
            int pat = 0;
            #pragma unroll
            for (int i = 0; i < G; i++) pat |= (int)((pw[i] >> p) & 1u) << i;
            atomicAdd(&s_hist[pat], 1);
        }
    }
    #pragma unroll
    for (int i = 0; i < G; i++) {
        int v = a_loc[i];
        #pragma unroll
        for (int o = 16; o; o >>= 1) v += __shfl_down_sync(0xffffffffu, v, o);
        if ((threadIdx.x & 31) == 0 && v) atomicAdd(&s_a[i], v);
    }
    __syncthreads();
    for (int i = threadIdx.x; i < HSIZE; i += TPB)
        if (s_hist[i]) atomicAdd(&g_hist[b][g][i], s_hist[i]);
    if (threadIdx.x < G && s_a[threadIdx.x]) atomicAdd(&g_interA[b][g][threadIdx.x], s_a[threadIdx.x]);
    __syncthreads();
    if (threadIdx.x == 0) {
        __threadfence();
        s_old = atomicAdd(&g_ticket[b][g], 1u);
    }
    __syncthreads();
    if (s_old != gridDim.x - 1) return;   // not the last block

    if (threadIdx.x >= 32) return;
    int lane = threadIdx.x;
    const int HL = HSIZE/32;
    int h[HL];
    #pragma unroll
    for (int k = 0; k < HL; k++) h[k] = __ldcg(&g_hist[b][g][lane*HL + k]);
    int keptm = 0;
    int iid = g_next_iid[b];
    int nk  = g_nkept[b];
    int base = g*G;
    for (int i = 0; i < G; i++) {
        int r = base + i;
        float s  = g_sscore[b][r];
        int area = g_area[b][r];
        int inter = __ldcg(&g_interA[b][g][i]);
        int loc = 0;
        #pragma unroll
        for (int k = 0; k < HL; k++) {
            int pat = lane*HL + k;
            if (((pat >> i) & 1) && (pat & keptm)) loc += h[k];
        }
        #pragma unroll
        for (int o = 16; o; o >>= 1) loc += __shfl_xor_sync(0xffffffffu, loc, o);
        inter += loc;
        bool keep = (s >= 0.5f) && (area > 0) && ((float)inter <= 0.5f * (float)area);
        if (keep) {
            if (lane == 0) {
                g_kept_rank[b][nk] = r;
                g_kept_val[b][nk]  = g_scls[b][r] + iid * 1000;
            }
            keptm |= 1 << i;
            iid++; nk++;
        }
    }
    if (lane == 0) {
        g_keptmask[b][g] = keptm;
        g_next_iid[b] = iid;
        g_nkept[b] = nk;
    }
}

// ---------------- stuff class histogram over unclaimed pixels ---------------
__global__ void k_stuff_hist(const unsigned int* __restrict__ sem) {
    int b = blockIdx.y;
    int w = blockIdx.x * TPB + threadIdx.x;
    int semf = g_sem_f32;
    __shared__ int s_cnt[NSEM];
    for (int i = threadIdx.x; i < NSEM; i += TPB) s_cnt[i] = 0;
    __syncthreads();
    if (w < WORDS) {
        uint32_t c = g_claimed[b][w];
        int km = g_keptmask[b][NG-1];
        int pbase = (NG-1)*G;
        while (km) { int i = __ffs(km) - 1; km &= km - 1; c |= g_planes[b][pbase+i][w]; }
        g_claimed[b][w] = c;   // now final claimed
        uint32_t u = ~c;
        const unsigned int* sp = sem + (size_t)b*PP + (size_t)w*32;
        while (u) {
            int p = __ffs(u) - 1; u &= u - 1;
            unsigned int raw = sp[p];
            int s = semf ? (int)__uint_as_float(raw) : (int)raw;
            if (s >= 0 && s < NSEM) atomicAdd(&s_cnt[s], 1);
        }
    }
    __syncthreads();
    for (int i = threadIdx.x; i < NSEM; i += TPB)
        if (s_cnt[i]) atomicAdd(&g_cls_counts[b][i], s_cnt[i]);
}

// ---------------- final output write ----------------------------------------
// OUTPUT IS ENCODED AS FLOAT32 VALUES (comparator reads the buffer as f32).
// All label values <= ~100079 are exactly representable in f32.
__global__ void k_final(const unsigned int* __restrict__ sem, int* __restrict__ out) {
    int b = blockIdx.y;
    int w = blockIdx.x * TPB + threadIdx.x;
    if (w >= WORDS) return;
    int semf = g_sem_f32;
    uint32_t c = g_claimed[b][w];
    int* op = out + (size_t)b*PP + (size_t)w*32;
    uint32_t rem = c;
    int nk = g_nkept[b];
    for (int k = 0; k < nk && rem; k++) {
        uint32_t m = g_planes[b][g_kept_rank[b][k]][w] & rem;
        if (m) {
            int st = __float_as_int((float)g_kept_val[b][k]);
            rem ^= m;
            while (m) { int p = __ffs(m) - 1; m &= m - 1; op[p] = st; }
        }
    }
    uint32_t u = ~c;
    const unsigned int* sp = sem + (size_t)b*PP + (size_t)w*32;
    while (u) {
        int p = __ffs(u) - 1; u &= u - 1;
        unsigned int raw = sp[p];
        int s = semf ? (int)__uint_as_float(raw) : (int)raw;
        int v = (s >= 0 && s < NSEM-1 && g_cls_counts[b][s] >= 4096) ? (s + 80) : 0;
        op[p] = __float_as_int((float)v);
    }
}

// ---------------- launch -----------------------------------------------------
extern "C" void kernel_launch(void* const* d_in, const int* in_sizes, int n_in,
                              void* d_out, int out_size) {
    // Map inputs by element count, order-agnostic.
    const void* masks = nullptr;
    const void* sem   = nullptr;
    const void* smallA = nullptr;
    const void* smallB = nullptr;
    for (int i = 0; i < n_in; i++) {
        if (in_sizes[i] == MASK_ELEMS)      masks = d_in[i];
        else if (in_sizes[i] == SEM_ELEMS)  sem   = d_in[i];
        else if (in_sizes[i] == BB*NN) {
            if (!smallA) smallA = d_in[i]; else smallB = d_in[i];
        }
    }
    if (!masks)  masks  = d_in[0];
    if (!smallA) smallA = d_in[1];
    if (!smallB) smallB = d_in[2];
    if (!sem)    sem    = d_in[3];
    int* out = (int*)d_out;

    k_init<<<256, 256>>>();
    k_detect<<<1, 256>>>((const unsigned int*)smallA, (const unsigned int*)smallB,
                         (const unsigned int*)sem, (const unsigned int*)masks);
    k_sort<<<1, 256>>>((const unsigned int*)smallA, (const unsigned int*)smallB);
    k_pack<<<dim3(WBLK, NN, BB), TPB>>>((const unsigned int*)masks);
    for (int g = 0; g < NG; g++)
        k_phase<<<dim3(WBLK, BB), TPB>>>(g);
    k_stuff_hist<<<dim3(WBLK, BB), TPB>>>((const unsigned int*)sem);
    k_final<<<dim3(WBLK, BB), TPB>>>((const unsigned int*)sem, out);
}